// round 2
// baseline (speedup 1.0000x reference)
#include <cuda_runtime.h>
#include <cstdint>
#include <math.h>

#define T_TOK 16384
#define H_DIM 1024
#define E_NUM 8
#define D_DIM 2048

// ---------------- device scratch (no allocations allowed) ----------------
__device__ int      g_cnt[E_NUM];
__device__ unsigned g_list[E_NUM * T_TOK];
__device__ double   g_psum[E_NUM];
__device__ double   g_entsum;
__device__ float    g_hbuf[(size_t)T_TOK * D_DIM];   // 134 MB intermediate h

// ---------------- helpers ----------------
__device__ __forceinline__ uint32_t cvt_tf32(float x) {
    uint32_t r;
    asm("cvt.rna.tf32.f32 %0, %1;" : "=r"(r) : "f"(x));
    return r;
}

__device__ __forceinline__ void mma_tf32(float c[4], const uint32_t a[4], const uint32_t b[2]) {
    asm volatile(
        "mma.sync.aligned.m16n8k8.row.col.f32.tf32.tf32.f32 "
        "{%0,%1,%2,%3}, {%4,%5,%6,%7}, {%8,%9}, {%0,%1,%2,%3};"
        : "+f"(c[0]), "+f"(c[1]), "+f"(c[2]), "+f"(c[3])
        : "r"(a[0]), "r"(a[1]), "r"(a[2]), "r"(a[3]), "r"(b[0]), "r"(b[1]));
}

__device__ __forceinline__ float gelu_exact(float v) {
    return 0.5f * v * (1.0f + erff(v * 0.70710678118654752440f));
}

// ---------------- init ----------------
__global__ void init_kernel() {
    int t = threadIdx.x;
    if (t < E_NUM) { g_cnt[t] = 0; g_psum[t] = 0.0; }
    if (t == 0) g_entsum = 0.0;
}

// ---------------- router: one warp per token ----------------
__global__ void router_kernel(const float* __restrict__ x,
                              const float* __restrict__ Wr,
                              const float* __restrict__ br) {
    __shared__ float WrT[E_NUM * H_DIM];   // transposed: [e][h], conflict-free reads
    __shared__ double s_psum[E_NUM];
    __shared__ double s_ent;

    int tid = threadIdx.x;
    for (int i = tid; i < E_NUM * H_DIM; i += blockDim.x) {
        int e = i >> 10, h = i & 1023;
        WrT[i] = Wr[h * E_NUM + e];
    }
    if (tid < E_NUM) s_psum[tid] = 0.0;
    if (tid == 0) s_ent = 0.0;
    __syncthreads();

    int warp = tid >> 5, lane = tid & 31;
    int t = blockIdx.x * 8 + warp;
    const float* xr = x + (size_t)t * H_DIM;

    float acc[E_NUM];
#pragma unroll
    for (int e = 0; e < E_NUM; e++) acc[e] = 0.f;
    for (int h = lane; h < H_DIM; h += 32) {
        float xv = xr[h];
#pragma unroll
        for (int e = 0; e < E_NUM; e++) acc[e] += xv * WrT[e * H_DIM + h];
    }
#pragma unroll
    for (int e = 0; e < E_NUM; e++) {
#pragma unroll
        for (int o = 16; o > 0; o >>= 1) acc[e] += __shfl_xor_sync(0xffffffffu, acc[e], o);
    }

    if (lane == 0) {
        float lg[E_NUM], p[E_NUM];
        float mx = -1e30f;
#pragma unroll
        for (int e = 0; e < E_NUM; e++) { lg[e] = acc[e] + br[e]; mx = fmaxf(mx, lg[e]); }
        float s = 0.f;
#pragma unroll
        for (int e = 0; e < E_NUM; e++) { p[e] = __expf(lg[e] - mx); s += p[e]; }
        float inv = 1.f / s;
        int amax = 0;
        float ent = 0.f;
#pragma unroll
        for (int e = 0; e < E_NUM; e++) {
            p[e] *= inv;
            if (lg[e] > lg[amax]) amax = e;            // first-max semantics
            ent -= p[e] * logf(p[e] + 1e-8f);
        }
        int pos = atomicAdd(&g_cnt[amax], 1);
        g_list[amax * T_TOK + pos] = (unsigned)t;
#pragma unroll
        for (int e = 0; e < E_NUM; e++) atomicAdd(&s_psum[e], (double)p[e]);
        atomicAdd(&s_ent, (double)ent);
    }
    __syncthreads();
    if (tid < E_NUM) atomicAdd(&g_psum[tid], s_psum[tid]);
    if (tid == 0) atomicAdd(&g_entsum, s_ent);
}

// ---------------- grouped GEMM (tf32 mma.sync), gathered rows by token ----------------
// GELU=true : C = gelu(x[tok] @ W1[e] + b1[e]) -> g_hbuf[tok]      (KD=1024, ND=2048)
// GELU=false: C = h[tok] @ W2[e] + b2[e] + x[tok] -> ext_out[tok]  (KD=2048, ND=1024)
template <int KD, int ND, bool GELU>
__global__ void __launch_bounds__(256)
ffn_gemm(const float* __restrict__ xin,
         const float* __restrict__ Wsrc,
         const float* __restrict__ bias,
         float* __restrict__ ext_out) {
    constexpr int BM = 128, BN = 128, BK = 16;
    constexpr int KT = KD / BK;

    int e = blockIdx.z;
    int cnt = g_cnt[e];
    int m0 = blockIdx.y * BM;
    if (m0 >= cnt) return;
    int n0 = blockIdx.x * BN;

    const float* Asrc = GELU ? xin : (const float*)g_hbuf;
    float* Outp       = GELU ? (float*)g_hbuf : ext_out;
    const float* W = Wsrc + (size_t)e * KD * ND;

    __shared__ __align__(16) float As[2][BM][20];    // k-stride 20: conflict-free frags
    __shared__ __align__(16) float Bs[2][BK][136];   // n-stride 136: conflict-free frags
    __shared__ unsigned tok_s[BM];
    __shared__ float bias_s[BN];

    int tid = threadIdx.x;
    if (tid < BM) {
        int i = m0 + tid;
        tok_s[tid] = (i < cnt) ? g_list[e * T_TOK + i] : 0xFFFFFFFFu;
    }
    if (tid < BN) bias_s[tid] = bias[e * ND + n0 + tid];
    __syncthreads();

    auto load_stage = [&](int s, int k0) {
#pragma unroll
        for (int j = 0; j < 2; j++) {                 // A: 128x16 fp32 = 512 float4
            int idx = tid + j * 256;
            int row = idx >> 2, c4 = idx & 3;
            unsigned tk = tok_s[row];
            const float* src = (tk != 0xFFFFFFFFu) ? (Asrc + (size_t)tk * KD + k0 + c4 * 4)
                                                   : Asrc;
            int zf = (tk != 0xFFFFFFFFu) ? 16 : 0;   // zero-fill padded rows
            uint32_t dst = (uint32_t)__cvta_generic_to_shared(&As[s][row][c4 * 4]);
            asm volatile("cp.async.cg.shared.global [%0], [%1], 16, %2;"
                         :: "r"(dst), "l"(src), "r"(zf));
        }
#pragma unroll
        for (int j = 0; j < 2; j++) {                 // B: 16x128 fp32 = 512 float4
            int idx = tid + j * 256;
            int kr = idx >> 5, n4 = idx & 31;
            const float* src = W + (size_t)(k0 + kr) * ND + n0 + n4 * 4;
            uint32_t dst = (uint32_t)__cvta_generic_to_shared(&Bs[s][kr][n4 * 4]);
            asm volatile("cp.async.cg.shared.global [%0], [%1], 16;"
                         :: "r"(dst), "l"(src));
        }
        asm volatile("cp.async.commit_group;");
    };

    int warp = tid >> 5, lane = tid & 31;
    int g = lane >> 2, tg = lane & 3;
    int wm = warp >> 2, wn = warp & 3;               // 2x4 warp grid, warp tile 64x32

    float c[4][4][4];
#pragma unroll
    for (int i = 0; i < 4; i++)
#pragma unroll
        for (int j = 0; j < 4; j++)
#pragma unroll
            for (int k = 0; k < 4; k++) c[i][j][k] = 0.f;

    load_stage(0, 0);
    for (int kt = 0; kt < KT; kt++) {
        if (kt + 1 < KT) {
            load_stage((kt + 1) & 1, (kt + 1) * BK);
            asm volatile("cp.async.wait_group 1;");
        } else {
            asm volatile("cp.async.wait_group 0;");
        }
        __syncthreads();
        int cur = kt & 1;
#pragma unroll
        for (int ks = 0; ks < 2; ks++) {
            int k8 = ks * 8;
            uint32_t a[4][4], b[4][2];
#pragma unroll
            for (int tm = 0; tm < 4; tm++) {
                int r = wm * 64 + tm * 16;
                a[tm][0] = cvt_tf32(As[cur][r + g][k8 + tg]);
                a[tm][1] = cvt_tf32(As[cur][r + 8 + g][k8 + tg]);
                a[tm][2] = cvt_tf32(As[cur][r + g][k8 + tg + 4]);
                a[tm][3] = cvt_tf32(As[cur][r + 8 + g][k8 + tg + 4]);
            }
#pragma unroll
            for (int tn = 0; tn < 4; tn++) {
                int nb = wn * 32 + tn * 8;
                b[tn][0] = cvt_tf32(Bs[cur][k8 + tg][nb + g]);
                b[tn][1] = cvt_tf32(Bs[cur][k8 + tg + 4][nb + g]);
            }
#pragma unroll
            for (int tm = 0; tm < 4; tm++)
#pragma unroll
                for (int tn = 0; tn < 4; tn++) mma_tf32(c[tm][tn], a[tm], b[tn]);
        }
        __syncthreads();
    }

    // epilogue
#pragma unroll
    for (int tm = 0; tm < 4; tm++) {
        int rbase = wm * 64 + tm * 16;
#pragma unroll
        for (int half = 0; half < 2; half++) {
            int rl = rbase + half * 8 + g;
            unsigned tk = tok_s[rl];
            if (tk == 0xFFFFFFFFu) continue;
            float* orow = Outp + (size_t)tk * ND;
            const float* xrow = GELU ? (const float*)0 : (xin + (size_t)tk * H_DIM);
#pragma unroll
            for (int tn = 0; tn < 4; tn++) {
                int cb = wn * 32 + tn * 8 + tg * 2;   // col within block tile
                float v0 = c[tm][tn][half * 2 + 0] + bias_s[cb];
                float v1 = c[tm][tn][half * 2 + 1] + bias_s[cb + 1];
                if (GELU) {
                    v0 = gelu_exact(v0);
                    v1 = gelu_exact(v1);
                } else {
                    float2 xv = *(const float2*)(xrow + n0 + cb);
                    v0 += xv.x;
                    v1 += xv.y;
                }
                *(float2*)(orow + n0 + cb) = make_float2(v0, v1);
            }
        }
    }
}

// ---------------- finalize: losses + counts ----------------
__global__ void finalize_kernel(float* out, int out_size) {
    if (threadIdx.x == 0) {
        long long base = (long long)T_TOK * H_DIM;
        if ((long long)out_size >= base + 10) {
            double bl = 0.0;
            for (int e = 0; e < E_NUM; e++) {
                double p = g_psum[e] / (double)T_TOK;
                bl += p * p;
            }
            out[base + 0] = (float)((double)E_NUM * bl);
            out[base + 1] = (float)(g_entsum / (double)T_TOK);
            for (int e = 0; e < E_NUM; e++) out[base + 2 + e] = (float)g_cnt[e];
        }
    }
}

// ---------------- launch ----------------
extern "C" void kernel_launch(void* const* d_in, const int* in_sizes, int n_in,
                              void* d_out, int out_size) {
    const float* x  = (const float*)d_in[0];
    const float* Wr = (const float*)d_in[1];
    const float* br = (const float*)d_in[2];
    const float* W1 = (const float*)d_in[3];
    const float* b1 = (const float*)d_in[4];
    const float* W2 = (const float*)d_in[5];
    const float* b2 = (const float*)d_in[6];
    float* out = (float*)d_out;

    init_kernel<<<1, 32>>>();
    router_kernel<<<T_TOK / 8, 256>>>(x, Wr, br);
    ffn_gemm<H_DIM, D_DIM, true ><<<dim3(D_DIM / 128, T_TOK / 128, E_NUM), 256>>>(x, W1, b1, out);
    ffn_gemm<D_DIM, H_DIM, false><<<dim3(H_DIM / 128, T_TOK / 128, E_NUM), 256>>>(x, W2, b2, out);
    finalize_kernel<<<1, 32>>>(out, out_size);
}

// round 4
// speedup vs baseline: 1.1215x; 1.1215x over previous
#include <cuda_runtime.h>
#include <cstdint>
#include <math.h>

#define T_TOK 16384
#define H_DIM 1024
#define E_NUM 8
#define D_DIM 2048

// ---------------- device scratch (no allocations allowed) ----------------
__device__ int      g_cnt[E_NUM];
__device__ unsigned g_list[E_NUM * T_TOK];
__device__ double   g_psum[E_NUM];
__device__ double   g_entsum;
__device__ float    g_hbuf[(size_t)T_TOK * D_DIM];   // 134 MB intermediate h

// ---------------- helpers ----------------
__device__ __forceinline__ void mma_tf32(float c[4], const uint32_t a[4], const uint32_t b[2]) {
    asm volatile(
        "mma.sync.aligned.m16n8k8.row.col.f32.tf32.tf32.f32 "
        "{%0,%1,%2,%3}, {%4,%5,%6,%7}, {%8,%9}, {%0,%1,%2,%3};"
        : "+f"(c[0]), "+f"(c[1]), "+f"(c[2]), "+f"(c[3])
        : "r"(a[0]), "r"(a[1]), "r"(a[2]), "r"(a[3]), "r"(b[0]), "r"(b[1]));
}

__device__ __forceinline__ float gelu_exact(float v) {
    return 0.5f * v * (1.0f + erff(v * 0.70710678118654752440f));
}

// ---------------- init ----------------
__global__ void init_kernel() {
    int t = threadIdx.x;
    if (t < E_NUM) { g_cnt[t] = 0; g_psum[t] = 0.0; }
    if (t == 0) g_entsum = 0.0;
}

// ---------------- router: one warp per token, float4 vectorized ----------------
__global__ void router_kernel(const float* __restrict__ x,
                              const float* __restrict__ Wr,
                              const float* __restrict__ br) {
    __shared__ float WrT[E_NUM * H_DIM];   // transposed: [e][h]
    __shared__ double s_psum[E_NUM];
    __shared__ double s_ent;

    int tid = threadIdx.x;
    for (int i = tid; i < E_NUM * H_DIM; i += blockDim.x) {
        int e = i >> 10, h = i & 1023;
        WrT[i] = Wr[h * E_NUM + e];
    }
    if (tid < E_NUM) s_psum[tid] = 0.0;
    if (tid == 0) s_ent = 0.0;
    __syncthreads();

    int warp = tid >> 5, lane = tid & 31;
    int t = blockIdx.x * 8 + warp;
    const float4* xr = (const float4*)(x + (size_t)t * H_DIM);

    float acc[E_NUM];
#pragma unroll
    for (int e = 0; e < E_NUM; e++) acc[e] = 0.f;
#pragma unroll
    for (int h4 = lane; h4 < H_DIM / 4; h4 += 32) {
        float4 xv = xr[h4];
#pragma unroll
        for (int e = 0; e < E_NUM; e++) {
            float4 w = ((const float4*)(WrT + e * H_DIM))[h4];
            acc[e] += xv.x * w.x + xv.y * w.y + xv.z * w.z + xv.w * w.w;
        }
    }
#pragma unroll
    for (int e = 0; e < E_NUM; e++) {
#pragma unroll
        for (int o = 16; o > 0; o >>= 1) acc[e] += __shfl_xor_sync(0xffffffffu, acc[e], o);
    }

    if (lane == 0) {
        float lg[E_NUM], p[E_NUM];
        float mx = -1e30f;
#pragma unroll
        for (int e = 0; e < E_NUM; e++) { lg[e] = acc[e] + br[e]; mx = fmaxf(mx, lg[e]); }
        float s = 0.f;
#pragma unroll
        for (int e = 0; e < E_NUM; e++) { p[e] = __expf(lg[e] - mx); s += p[e]; }
        float inv = 1.f / s;
        int amax = 0;
        float ent = 0.f;
#pragma unroll
        for (int e = 0; e < E_NUM; e++) {
            p[e] *= inv;
            if (lg[e] > lg[amax]) amax = e;            // first-max semantics
            ent -= p[e] * logf(p[e] + 1e-8f);
        }
        int pos = atomicAdd(&g_cnt[amax], 1);
        g_list[amax * T_TOK + pos] = (unsigned)t;
#pragma unroll
        for (int e = 0; e < E_NUM; e++) atomicAdd(&s_psum[e], (double)p[e]);
        atomicAdd(&s_ent, (double)ent);
    }
    __syncthreads();
    if (tid < E_NUM) atomicAdd(&g_psum[tid], s_psum[tid]);
    if (tid == 0) atomicAdd(&g_entsum, s_ent);
}

// ---------------- grouped GEMM (tf32 mma.sync, raw fp32 bits, 4-stage pipe) ----------------
// GELU=true : C = gelu(x[tok] @ W1[e] + b1[e]) -> g_hbuf[tok]      (KD=1024, ND=2048)
// GELU=false: C = h[tok] @ W2[e] + b2[e] + x[tok] -> ext_out[tok]  (KD=2048, ND=1024)
template <int KD, int ND, bool GELU>
__global__ void __launch_bounds__(256)
ffn_gemm(const float* __restrict__ xin,
         const float* __restrict__ Wsrc,
         const float* __restrict__ bias,
         float* __restrict__ ext_out) {
    constexpr int BM = 128, BN = 128, BK = 16;
    constexpr int KT = KD / BK;
    constexpr int STG = 4;

    int e = blockIdx.z;
    int cnt = g_cnt[e];
    int m0 = blockIdx.y * BM;
    if (m0 >= cnt) return;
    int n0 = blockIdx.x * BN;

    const float* Asrc = GELU ? xin : (const float*)g_hbuf;
    float* Outp       = GELU ? (float*)g_hbuf : ext_out;
    const float* W = Wsrc + (size_t)e * KD * ND;

    __shared__ __align__(16) float As[STG][BM][20];    // k-stride 20: conflict-free frags
    __shared__ __align__(16) float Bs[STG][BK][136];   // n-stride 136: conflict-free frags
    __shared__ unsigned tok_s[BM];
    __shared__ float bias_s[BN];

    int tid = threadIdx.x;
    if (tid < BM) {
        int i = m0 + tid;
        tok_s[tid] = (i < cnt) ? g_list[e * T_TOK + i] : 0xFFFFFFFFu;
    }
    if (tid < BN) bias_s[tid] = bias[e * ND + n0 + tid];
    __syncthreads();

    auto load_stage = [&](int s, int k0) {
#pragma unroll
        for (int j = 0; j < 2; j++) {                 // A: 128x16 fp32 = 512 float4
            int idx = tid + j * 256;
            int row = idx >> 2, c4 = idx & 3;
            unsigned tk = tok_s[row];
            const float* src = (tk != 0xFFFFFFFFu) ? (Asrc + (size_t)tk * KD + k0 + c4 * 4)
                                                   : Asrc;
            int zf = (tk != 0xFFFFFFFFu) ? 16 : 0;   // zero-fill padded rows
            uint32_t dst = (uint32_t)__cvta_generic_to_shared(&As[s][row][c4 * 4]);
            asm volatile("cp.async.cg.shared.global [%0], [%1], 16, %2;"
                         :: "r"(dst), "l"(src), "r"(zf));
        }
#pragma unroll
        for (int j = 0; j < 2; j++) {                 // B: 16x128 fp32 = 512 float4
            int idx = tid + j * 256;
            int kr = idx >> 5, n4 = idx & 31;
            const float* src = W + (size_t)(k0 + kr) * ND + n0 + n4 * 4;
            uint32_t dst = (uint32_t)__cvta_generic_to_shared(&Bs[s][kr][n4 * 4]);
            asm volatile("cp.async.cg.shared.global [%0], [%1], 16;"
                         :: "r"(dst), "l"(src));
        }
        asm volatile("cp.async.commit_group;");
    };

    int warp = tid >> 5, lane = tid & 31;
    int g = lane >> 2, tg = lane & 3;
    int wm = warp >> 2, wn = warp & 3;               // 2x4 warp grid, warp tile 64x32

    float c[4][4][4];
#pragma unroll
    for (int i = 0; i < 4; i++)
#pragma unroll
        for (int j = 0; j < 4; j++)
#pragma unroll
            for (int k = 0; k < 4; k++) c[i][j][k] = 0.f;

    // prologue: fill STG-1 stages
    load_stage(0, 0);
    load_stage(1, BK);
    load_stage(2, 2 * BK);

    int cur = 0, nxt = 3;                            // stage indices mod STG
    for (int kt = 0; kt < KT; kt++) {
        int rem = KT - 1 - kt;
        if (rem >= 2)       asm volatile("cp.async.wait_group 2;");
        else if (rem == 1)  asm volatile("cp.async.wait_group 1;");
        else                asm volatile("cp.async.wait_group 0;");
        __syncthreads();                              // single barrier per iter

        if (kt + 3 < KT) {                            // overwrite stage consumed at kt-1
            load_stage(nxt, (kt + 3) * BK);
            if (++nxt == STG) nxt = 0;
        }

#pragma unroll
        for (int ks = 0; ks < 2; ks++) {
            int k8 = ks * 8;
            uint32_t a[4][4], b[4][2];
#pragma unroll
            for (int tm = 0; tm < 4; tm++) {
                int r = wm * 64 + tm * 16;
                a[tm][0] = __float_as_uint(As[cur][r + g][k8 + tg]);
                a[tm][1] = __float_as_uint(As[cur][r + 8 + g][k8 + tg]);
                a[tm][2] = __float_as_uint(As[cur][r + g][k8 + tg + 4]);
                a[tm][3] = __float_as_uint(As[cur][r + 8 + g][k8 + tg + 4]);
            }
#pragma unroll
            for (int tn = 0; tn < 4; tn++) {
                int nb = wn * 32 + tn * 8;
                b[tn][0] = __float_as_uint(Bs[cur][k8 + tg][nb + g]);
                b[tn][1] = __float_as_uint(Bs[cur][k8 + tg + 4][nb + g]);
            }
#pragma unroll
            for (int tm = 0; tm < 4; tm++)
#pragma unroll
                for (int tn = 0; tn < 4; tn++) mma_tf32(c[tm][tn], a[tm], b[tn]);
        }
        if (++cur == STG) cur = 0;
    }

    // epilogue
#pragma unroll
    for (int tm = 0; tm < 4; tm++) {
        int rbase = wm * 64 + tm * 16;
#pragma unroll
        for (int half = 0; half < 2; half++) {
            int rl = rbase + half * 8 + g;
            unsigned tk = tok_s[rl];
            if (tk == 0xFFFFFFFFu) continue;
            float* orow = Outp + (size_t)tk * ND;
            const float* xrow = GELU ? (const float*)0 : (xin + (size_t)tk * H_DIM);
#pragma unroll
            for (int tn = 0; tn < 4; tn++) {
                int cb = wn * 32 + tn * 8 + tg * 2;   // col within block tile
                float v0 = c[tm][tn][half * 2 + 0] + bias_s[cb];
                float v1 = c[tm][tn][half * 2 + 1] + bias_s[cb + 1];
                if (GELU) {
                    v0 = gelu_exact(v0);
                    v1 = gelu_exact(v1);
                } else {
                    float2 xv = *(const float2*)(xrow + n0 + cb);
                    v0 += xv.x;
                    v1 += xv.y;
                }
                *(float2*)(orow + n0 + cb) = make_float2(v0, v1);
            }
        }
    }
}

// ---------------- finalize: losses + counts ----------------
__global__ void finalize_kernel(float* out, int out_size) {
    if (threadIdx.x == 0) {
        long long base = (long long)T_TOK * H_DIM;
        if ((long long)out_size >= base + 10) {
            double bl = 0.0;
            for (int e = 0; e < E_NUM; e++) {
                double p = g_psum[e] / (double)T_TOK;
                bl += p * p;
            }
            out[base + 0] = (float)((double)E_NUM * bl);
            out[base + 1] = (float)(g_entsum / (double)T_TOK);
            for (int e = 0; e < E_NUM; e++) out[base + 2 + e] = (float)g_cnt[e];
        }
    }
}

// ---------------- launch ----------------
extern "C" void kernel_launch(void* const* d_in, const int* in_sizes, int n_in,
                              void* d_out, int out_size) {
    const float* x  = (const float*)d_in[0];
    const float* Wr = (const float*)d_in[1];
    const float* br = (const float*)d_in[2];
    const float* W1 = (const float*)d_in[3];
    const float* b1 = (const float*)d_in[4];
    const float* W2 = (const float*)d_in[5];
    const float* b2 = (const float*)d_in[6];
    float* out = (float*)d_out;

    init_kernel<<<1, 32>>>();
    router_kernel<<<T_TOK / 8, 256>>>(x, Wr, br);
    ffn_gemm<H_DIM, D_DIM, true ><<<dim3(D_DIM / 128, T_TOK / 128, E_NUM), 256>>>(x, W1, b1, out);
    ffn_gemm<D_DIM, H_DIM, false><<<dim3(H_DIM / 128, T_TOK / 128, E_NUM), 256>>>(x, W2, b2, out);
    finalize_kernel<<<1, 32>>>(out, out_size);
}

// round 9
// speedup vs baseline: 1.1405x; 1.0170x over previous
#include <cuda_runtime.h>
#include <cstdint>
#include <math.h>

#define T_TOK 16384
#define H_DIM 1024
#define E_NUM 8
#define D_DIM 2048

// ---------------- device scratch (no allocations allowed) ----------------
__device__ int      g_cnt[E_NUM];
__device__ unsigned g_list[E_NUM * T_TOK];
__device__ double   g_psum[E_NUM];
__device__ double   g_entsum;
__device__ float    g_hbuf[(size_t)T_TOK * D_DIM];   // 134 MB intermediate h

// ---------------- helpers ----------------
__device__ __forceinline__ void mma_tf32(float c[4], const uint32_t a[4], const uint32_t b[2]) {
    asm volatile(
        "mma.sync.aligned.m16n8k8.row.col.f32.tf32.tf32.f32 "
        "{%0,%1,%2,%3}, {%4,%5,%6,%7}, {%8,%9}, {%0,%1,%2,%3};"
        : "+f"(c[0]), "+f"(c[1]), "+f"(c[2]), "+f"(c[3])
        : "r"(a[0]), "r"(a[1]), "r"(a[2]), "r"(a[3]), "r"(b[0]), "r"(b[1]));
}

__device__ __forceinline__ float gelu_exact(float v) {
    return 0.5f * v * (1.0f + erff(v * 0.70710678118654752440f));
}

// ---------------- init ----------------
__global__ void init_kernel() {
    int t = threadIdx.x;
    if (t < E_NUM) { g_cnt[t] = 0; g_psum[t] = 0.0; }
    if (t == 0) g_entsum = 0.0;
}

// ---------------- router: one warp per token, float4 vectorized ----------------
__global__ void router_kernel(const float* __restrict__ x,
                              const float* __restrict__ Wr,
                              const float* __restrict__ br) {
    __shared__ float WrT[E_NUM * H_DIM];
    __shared__ double s_psum[E_NUM];
    __shared__ double s_ent;

    int tid = threadIdx.x;
    for (int i = tid; i < E_NUM * H_DIM; i += blockDim.x) {
        int e = i >> 10, h = i & 1023;
        WrT[i] = Wr[h * E_NUM + e];
    }
    if (tid < E_NUM) s_psum[tid] = 0.0;
    if (tid == 0) s_ent = 0.0;
    __syncthreads();

    int warp = tid >> 5, lane = tid & 31;
    int t = blockIdx.x * 8 + warp;
    const float4* xr = (const float4*)(x + (size_t)t * H_DIM);

    float acc[E_NUM];
#pragma unroll
    for (int e = 0; e < E_NUM; e++) acc[e] = 0.f;
#pragma unroll
    for (int h4 = lane; h4 < H_DIM / 4; h4 += 32) {
        float4 xv = xr[h4];
#pragma unroll
        for (int e = 0; e < E_NUM; e++) {
            float4 w = ((const float4*)(WrT + e * H_DIM))[h4];
            acc[e] += xv.x * w.x + xv.y * w.y + xv.z * w.z + xv.w * w.w;
        }
    }
#pragma unroll
    for (int e = 0; e < E_NUM; e++) {
#pragma unroll
        for (int o = 16; o > 0; o >>= 1) acc[e] += __shfl_xor_sync(0xffffffffu, acc[e], o);
    }

    if (lane == 0) {
        float lg[E_NUM], p[E_NUM];
        float mx = -1e30f;
#pragma unroll
        for (int e = 0; e < E_NUM; e++) { lg[e] = acc[e] + br[e]; mx = fmaxf(mx, lg[e]); }
        float s = 0.f;
#pragma unroll
        for (int e = 0; e < E_NUM; e++) { p[e] = __expf(lg[e] - mx); s += p[e]; }
        float inv = 1.f / s;
        int amax = 0;
        float ent = 0.f;
#pragma unroll
        for (int e = 0; e < E_NUM; e++) {
            p[e] *= inv;
            if (lg[e] > lg[amax]) amax = e;            // first-max semantics
            ent -= p[e] * logf(p[e] + 1e-8f);
        }
        int pos = atomicAdd(&g_cnt[amax], 1);
        g_list[amax * T_TOK + pos] = (unsigned)t;
#pragma unroll
        for (int e = 0; e < E_NUM; e++) atomicAdd(&s_psum[e], (double)p[e]);
        atomicAdd(&s_ent, (double)ent);
    }
    __syncthreads();
    if (tid < E_NUM) atomicAdd(&g_psum[tid], s_psum[tid]);
    if (tid == 0) atomicAdd(&g_entsum, s_ent);
}

// ---------------- grouped GEMM: CTA 128x256, warp tile 64x64, BK=32 double-buffer ----------------
// GELU=true : h = gelu(x[tok] @ W1[e] + b1[e]) -> g_hbuf   (KD=1024, ND=2048)
// GELU=false: out = h[tok] @ W2[e] + b2[e] + x -> ext_out  (KD=2048, ND=1024)
// smem per stage: A 128 x 36f (rows 144B, bank 4g+tg) + B 32 x 264f (rows 1056B, bank 8tg+g)
template <int KD, int ND, bool GELU>
__global__ void __launch_bounds__(256, 1)
ffn_gemm(const float* __restrict__ xin,
         const float* __restrict__ Wsrc,
         const float* __restrict__ bias,
         float* __restrict__ ext_out) {
    constexpr int BM = 128, BN = 256, BK = 32;
    constexpr int KT = KD / BK;
    constexpr int AS = 36;                 // A k-stride (floats)
    constexpr int BS = 264;                // B n-stride (floats)
    constexpr int A_BYTES = BM * AS * 4;   // 18432
    constexpr int STAGE = A_BYTES + BK * BS * 4;   // 18432 + 33792 = 52224

    int e = blockIdx.z;
    int cnt = g_cnt[e];
    int m0 = blockIdx.y * BM;
    if (m0 >= cnt) return;
    int n0 = blockIdx.x * BN;

    const float* Asrc = GELU ? xin : (const float*)g_hbuf;
    float* Outp       = GELU ? (float*)g_hbuf : ext_out;
    const float* W = Wsrc + (size_t)e * KD * ND;

    extern __shared__ __align__(16) char smem[];
    unsigned* tok_s = (unsigned*)(smem + 2 * STAGE);          // 128 * 4B
    float*   bias_s = (float*)(smem + 2 * STAGE + 512);       // 256 * 4B

    int tid = threadIdx.x;
    if (tid < BM) {
        int i = m0 + tid;
        tok_s[tid] = (i < cnt) ? g_list[e * T_TOK + i] : 0xFFFFFFFFu;
    }
    bias_s[tid] = bias[e * ND + n0 + tid];
    __syncthreads();

    auto fill = [&](int s, int k0) {
        char* ab = smem + s * STAGE;
        char* bb = ab + A_BYTES;
#pragma unroll
        for (int j = 0; j < 4; j++) {                 // A: 128 rows x 32 k = 1024 float4
            int idx = tid + j * 256;
            int row = idx >> 3, c = idx & 7;
            unsigned tk = tok_s[row];
            const float* src = (tk != 0xFFFFFFFFu) ? (Asrc + (size_t)tk * KD + k0 + c * 4)
                                                   : Asrc;
            int zf = (tk != 0xFFFFFFFFu) ? 16 : 0;
            uint32_t dst = (uint32_t)__cvta_generic_to_shared(ab + row * (AS * 4) + c * 16);
            asm volatile("cp.async.cg.shared.global [%0], [%1], 16, %2;"
                         :: "r"(dst), "l"(src), "r"(zf));
        }
#pragma unroll
        for (int j = 0; j < 8; j++) {                 // B: 32 k-rows x 256 n = 2048 float4
            int idx = tid + j * 256;
            int kr = idx >> 6, n4 = idx & 63;
            const float* src = W + (size_t)(k0 + kr) * ND + n0 + n4 * 4;
            uint32_t dst = (uint32_t)__cvta_generic_to_shared(bb + kr * (BS * 4) + n4 * 16);
            asm volatile("cp.async.cg.shared.global [%0], [%1], 16;"
                         :: "r"(dst), "l"(src));
        }
        asm volatile("cp.async.commit_group;");
    };

    int warp = tid >> 5, lane = tid & 31;
    int g = lane >> 2, tg = lane & 3;
    int wm = warp >> 2, wn = warp & 3;               // 2x4 warp grid, warp tile 64x64

    float c[4][8][4];
#pragma unroll
    for (int i = 0; i < 4; i++)
#pragma unroll
        for (int j = 0; j < 8; j++)
#pragma unroll
            for (int k = 0; k < 4; k++) c[i][j][k] = 0.f;

    fill(0, 0);

    int s = 0;
    for (int kt = 0; kt < KT; kt++) {
        asm volatile("cp.async.wait_group 0;");
        __syncthreads();                              // stage s ready; 1-s fully consumed
        if (kt + 1 < KT) fill(1 - s, (kt + 1) * BK);  // prefetch overlaps compute below

        const float* Ab = (const float*)(smem + s * STAGE);
        const float* Bb = (const float*)(smem + s * STAGE + A_BYTES);
#pragma unroll
        for (int ks = 0; ks < 4; ks++) {
            int k8 = ks * 8;
            uint32_t a[4][4], b[8][2];
#pragma unroll
            for (int tm = 0; tm < 4; tm++) {
                int r = wm * 64 + tm * 16;
                a[tm][0] = __float_as_uint(Ab[(r + g) * AS + k8 + tg]);
                a[tm][1] = __float_as_uint(Ab[(r + 8 + g) * AS + k8 + tg]);
                a[tm][2] = __float_as_uint(Ab[(r + g) * AS + k8 + tg + 4]);
                a[tm][3] = __float_as_uint(Ab[(r + 8 + g) * AS + k8 + tg + 4]);
            }
#pragma unroll
            for (int tn = 0; tn < 8; tn++) {
                int nb = wn * 64 + tn * 8;
                b[tn][0] = __float_as_uint(Bb[(k8 + tg) * BS + nb + g]);
                b[tn][1] = __float_as_uint(Bb[(k8 + tg + 4) * BS + nb + g]);
            }
#pragma unroll
            for (int tm = 0; tm < 4; tm++)
#pragma unroll
                for (int tn = 0; tn < 8; tn++) mma_tf32(c[tm][tn], a[tm], b[tn]);
        }
        s ^= 1;
    }

    // ---------------- epilogue ----------------
#pragma unroll
    for (int tm = 0; tm < 4; tm++) {
        int rbase = wm * 64 + tm * 16;
#pragma unroll
        for (int half = 0; half < 2; half++) {
            int rl = rbase + half * 8 + g;
            unsigned tk = tok_s[rl];
            if (tk == 0xFFFFFFFFu) continue;
            float* orow = Outp + (size_t)tk * ND;
            const float* xrow = GELU ? (const float*)0 : (xin + (size_t)tk * H_DIM);
#pragma unroll
            for (int tn = 0; tn < 8; tn++) {
                int cb = wn * 64 + tn * 8 + tg * 2;
                float v0 = c[tm][tn][half * 2 + 0] + bias_s[cb];
                float v1 = c[tm][tn][half * 2 + 1] + bias_s[cb + 1];
                if (GELU) {
                    v0 = gelu_exact(v0);
                    v1 = gelu_exact(v1);
                } else {
                    float2 xv = *(const float2*)(xrow + n0 + cb);
                    v0 += xv.x;
                    v1 += xv.y;
                }
                *(float2*)(orow + n0 + cb) = make_float2(v0, v1);
            }
        }
    }
}

// ---------------- finalize: losses + counts ----------------
__global__ void finalize_kernel(float* out, int out_size) {
    if (threadIdx.x == 0) {
        long long base = (long long)T_TOK * H_DIM;
        if ((long long)out_size >= base + 10) {
            double bl = 0.0;
            for (int e = 0; e < E_NUM; e++) {
                double p = g_psum[e] / (double)T_TOK;
                bl += p * p;
            }
            out[base + 0] = (float)((double)E_NUM * bl);
            out[base + 1] = (float)(g_entsum / (double)T_TOK);
            for (int e = 0; e < E_NUM; e++) out[base + 2 + e] = (float)g_cnt[e];
        }
    }
}

// ---------------- launch ----------------
extern "C" void kernel_launch(void* const* d_in, const int* in_sizes, int n_in,
                              void* d_out, int out_size) {
    const float* x  = (const float*)d_in[0];
    const float* Wr = (const float*)d_in[1];
    const float* br = (const float*)d_in[2];
    const float* W1 = (const float*)d_in[3];
    const float* b1 = (const float*)d_in[4];
    const float* W2 = (const float*)d_in[5];
    const float* b2 = (const float*)d_in[6];
    float* out = (float*)d_out;

    const int SMEM_BYTES = 2 * 52224 + 512 + 1024;   // 105,984

    cudaFuncSetAttribute(ffn_gemm<H_DIM, D_DIM, true >,
                         cudaFuncAttributeMaxDynamicSharedMemorySize, SMEM_BYTES);
    cudaFuncSetAttribute(ffn_gemm<D_DIM, H_DIM, false>,
                         cudaFuncAttributeMaxDynamicSharedMemorySize, SMEM_BYTES);

    init_kernel<<<1, 32>>>();
    router_kernel<<<T_TOK / 8, 256>>>(x, Wr, br);
    ffn_gemm<H_DIM, D_DIM, true ><<<dim3(D_DIM / 256, T_TOK / 128, E_NUM), 256, SMEM_BYTES>>>(x, W1, b1, out);
    ffn_gemm<D_DIM, H_DIM, false><<<dim3(H_DIM / 256, T_TOK / 128, E_NUM), 256, SMEM_BYTES>>>(x, W2, b2, out);
    finalize_kernel<<<1, 32>>>(out, out_size);
}

// round 14
// speedup vs baseline: 1.1416x; 1.0010x over previous
#include <cuda_runtime.h>
#include <cstdint>
#include <math.h>

#define T_TOK 16384
#define H_DIM 1024
#define E_NUM 8
#define D_DIM 2048

// ---------------- device scratch (no allocations allowed) ----------------
__device__ int      g_cnt[E_NUM];
__device__ unsigned g_list[E_NUM * T_TOK];
__device__ double   g_psum[E_NUM];
__device__ double   g_entsum;
__device__ float    g_hbuf[(size_t)T_TOK * D_DIM];   // 134 MB intermediate h

// ---------------- helpers ----------------
__device__ __forceinline__ void mma_tf32(float c[4], const uint32_t a[4], const uint32_t b[2]) {
    asm volatile(
        "mma.sync.aligned.m16n8k8.row.col.f32.tf32.tf32.f32 "
        "{%0,%1,%2,%3}, {%4,%5,%6,%7}, {%8,%9}, {%0,%1,%2,%3};"
        : "+f"(c[0]), "+f"(c[1]), "+f"(c[2]), "+f"(c[3])
        : "r"(a[0]), "r"(a[1]), "r"(a[2]), "r"(a[3]), "r"(b[0]), "r"(b[1]));
}

__device__ __forceinline__ float gelu_exact(float v) {
    return 0.5f * v * (1.0f + erff(v * 0.70710678118654752440f));
}

// ---------------- init ----------------
__global__ void init_kernel() {
    int t = threadIdx.x;
    if (t < E_NUM) { g_cnt[t] = 0; g_psum[t] = 0.0; }
    if (t == 0) g_entsum = 0.0;
}

// ---------------- router: one warp per token, float4 vectorized ----------------
__global__ void router_kernel(const float* __restrict__ x,
                              const float* __restrict__ Wr,
                              const float* __restrict__ br) {
    __shared__ float WrT[E_NUM * H_DIM];
    __shared__ double s_psum[E_NUM];
    __shared__ double s_ent;

    int tid = threadIdx.x;
    for (int i = tid; i < E_NUM * H_DIM; i += blockDim.x) {
        int e = i >> 10, h = i & 1023;
        WrT[i] = Wr[h * E_NUM + e];
    }
    if (tid < E_NUM) s_psum[tid] = 0.0;
    if (tid == 0) s_ent = 0.0;
    __syncthreads();

    int warp = tid >> 5, lane = tid & 31;
    int t = blockIdx.x * 8 + warp;
    const float4* xr = (const float4*)(x + (size_t)t * H_DIM);

    float acc[E_NUM];
#pragma unroll
    for (int e = 0; e < E_NUM; e++) acc[e] = 0.f;
#pragma unroll
    for (int h4 = lane; h4 < H_DIM / 4; h4 += 32) {
        float4 xv = xr[h4];
#pragma unroll
        for (int e = 0; e < E_NUM; e++) {
            float4 w = ((const float4*)(WrT + e * H_DIM))[h4];
            acc[e] += xv.x * w.x + xv.y * w.y + xv.z * w.z + xv.w * w.w;
        }
    }
#pragma unroll
    for (int e = 0; e < E_NUM; e++) {
#pragma unroll
        for (int o = 16; o > 0; o >>= 1) acc[e] += __shfl_xor_sync(0xffffffffu, acc[e], o);
    }

    if (lane == 0) {
        float lg[E_NUM], p[E_NUM];
        float mx = -1e30f;
#pragma unroll
        for (int e = 0; e < E_NUM; e++) { lg[e] = acc[e] + br[e]; mx = fmaxf(mx, lg[e]); }
        float s = 0.f;
#pragma unroll
        for (int e = 0; e < E_NUM; e++) { p[e] = __expf(lg[e] - mx); s += p[e]; }
        float inv = 1.f / s;
        int amax = 0;
        float ent = 0.f;
#pragma unroll
        for (int e = 0; e < E_NUM; e++) {
            p[e] *= inv;
            if (lg[e] > lg[amax]) amax = e;            // first-max semantics
            ent -= p[e] * logf(p[e] + 1e-8f);
        }
        int pos = atomicAdd(&g_cnt[amax], 1);
        g_list[amax * T_TOK + pos] = (unsigned)t;
#pragma unroll
        for (int e = 0; e < E_NUM; e++) atomicAdd(&s_psum[e], (double)p[e]);
        atomicAdd(&s_ent, (double)ent);
    }
    __syncthreads();
    if (tid < E_NUM) atomicAdd(&g_psum[tid], s_psum[tid]);
    if (tid == 0) atomicAdd(&g_entsum, s_ent);
}

// ---------------- grouped GEMM: CTA 128x256, warp tile 64x64, BK=32, 3-stage pipe ----------------
// GELU=true : h = gelu(x[tok] @ W1[e] + b1[e]) -> g_hbuf   (KD=1024, ND=2048)
// GELU=false: out = h[tok] @ W2[e] + b2[e] + x -> ext_out  (KD=2048, ND=1024)
// smem per stage: A 128 x 36f (bank 4g+tg) + B 32 x 264f (bank 8tg+g) — conflict-free
template <int KD, int ND, bool GELU>
__global__ void __launch_bounds__(256, 1)
ffn_gemm(const float* __restrict__ xin,
         const float* __restrict__ Wsrc,
         const float* __restrict__ bias,
         float* __restrict__ ext_out) {
    constexpr int BM = 128, BN = 256, BK = 32;
    constexpr int KT = KD / BK;
    constexpr int STG = 3;
    constexpr int AS = 36;                 // A k-stride (floats)
    constexpr int BS = 264;                // B n-stride (floats)
    constexpr int A_BYTES = BM * AS * 4;   // 18432
    constexpr int STAGE = A_BYTES + BK * BS * 4;   // 52224

    int e = blockIdx.z;
    int cnt = g_cnt[e];
    int m0 = blockIdx.y * BM;
    if (m0 >= cnt) return;
    int n0 = blockIdx.x * BN;

    const float* Asrc = GELU ? xin : (const float*)g_hbuf;
    float* Outp       = GELU ? (float*)g_hbuf : ext_out;
    const float* W = Wsrc + (size_t)e * KD * ND;

    extern __shared__ __align__(16) char smem[];
    unsigned* tok_s = (unsigned*)(smem + STG * STAGE);        // 128 * 4B
    float*   bias_s = (float*)(smem + STG * STAGE + 512);     // 256 * 4B

    int tid = threadIdx.x;
    if (tid < BM) {
        int i = m0 + tid;
        tok_s[tid] = (i < cnt) ? g_list[e * T_TOK + i] : 0xFFFFFFFFu;
    }
    bias_s[tid] = bias[e * ND + n0 + tid];
    __syncthreads();

    auto fill = [&](int s, int k0) {
        char* ab = smem + s * STAGE;
        char* bb = ab + A_BYTES;
#pragma unroll
        for (int j = 0; j < 4; j++) {                 // A: 128 rows x 32 k = 1024 float4
            int idx = tid + j * 256;
            int row = idx >> 3, c = idx & 7;
            unsigned tk = tok_s[row];
            const float* src = (tk != 0xFFFFFFFFu) ? (Asrc + (size_t)tk * KD + k0 + c * 4)
                                                   : Asrc;
            int zf = (tk != 0xFFFFFFFFu) ? 16 : 0;
            uint32_t dst = (uint32_t)__cvta_generic_to_shared(ab + row * (AS * 4) + c * 16);
            asm volatile("cp.async.cg.shared.global [%0], [%1], 16, %2;"
                         :: "r"(dst), "l"(src), "r"(zf));
        }
#pragma unroll
        for (int j = 0; j < 8; j++) {                 // B: 32 k-rows x 256 n = 2048 float4
            int idx = tid + j * 256;
            int kr = idx >> 6, n4 = idx & 63;
            const float* src = W + (size_t)(k0 + kr) * ND + n0 + n4 * 4;
            uint32_t dst = (uint32_t)__cvta_generic_to_shared(bb + kr * (BS * 4) + n4 * 16);
            asm volatile("cp.async.cg.shared.global [%0], [%1], 16;"
                         :: "r"(dst), "l"(src));
        }
        asm volatile("cp.async.commit_group;");
    };

    int warp = tid >> 5, lane = tid & 31;
    int g = lane >> 2, tg = lane & 3;
    int wm = warp >> 2, wn = warp & 3;               // 2x4 warp grid, warp tile 64x64

    float c[4][8][4];
#pragma unroll
    for (int i = 0; i < 4; i++)
#pragma unroll
        for (int j = 0; j < 8; j++)
#pragma unroll
            for (int k = 0; k < 4; k++) c[i][j][k] = 0.f;

    // prologue: 2 stages in flight
    fill(0, 0);
    fill(1, BK);

    int s = 0;
    for (int kt = 0; kt < KT; kt++) {
        // stage kt must be complete; allow the newest group to stay in flight
        if (kt + 1 < KT) asm volatile("cp.async.wait_group 1;");
        else             asm volatile("cp.async.wait_group 0;");
        __syncthreads();                              // all warps past compute(kt-1) -> stage (kt+2)%3 free

        if (kt + 2 < KT) fill((kt + 2) % STG, (kt + 2) * BK);

        const float* Ab = (const float*)(smem + s * STAGE);
        const float* Bb = (const float*)(smem + s * STAGE + A_BYTES);
#pragma unroll
        for (int ks = 0; ks < 4; ks++) {
            int k8 = ks * 8;
            uint32_t a[4][4], b[8][2];
#pragma unroll
            for (int tm = 0; tm < 4; tm++) {
                int r = wm * 64 + tm * 16;
                a[tm][0] = __float_as_uint(Ab[(r + g) * AS + k8 + tg]);
                a[tm][1] = __float_as_uint(Ab[(r + 8 + g) * AS + k8 + tg]);
                a[tm][2] = __float_as_uint(Ab[(r + g) * AS + k8 + tg + 4]);
                a[tm][3] = __float_as_uint(Ab[(r + 8 + g) * AS + k8 + tg + 4]);
            }
#pragma unroll
            for (int tn = 0; tn < 8; tn++) {
                int nb = wn * 64 + tn * 8;
                b[tn][0] = __float_as_uint(Bb[(k8 + tg) * BS + nb + g]);
                b[tn][1] = __float_as_uint(Bb[(k8 + tg + 4) * BS + nb + g]);
            }
#pragma unroll
            for (int tm = 0; tm < 4; tm++)
#pragma unroll
                for (int tn = 0; tn < 8; tn++) mma_tf32(c[tm][tn], a[tm], b[tn]);
        }
        if (++s == STG) s = 0;
    }

    // ---------------- epilogue ----------------
#pragma unroll
    for (int tm = 0; tm < 4; tm++) {
        int rbase = wm * 64 + tm * 16;
#pragma unroll
        for (int half = 0; half < 2; half++) {
            int rl = rbase + half * 8 + g;
            unsigned tk = tok_s[rl];
            if (tk == 0xFFFFFFFFu) continue;
            float* orow = Outp + (size_t)tk * ND;
            const float* xrow = GELU ? (const float*)0 : (xin + (size_t)tk * H_DIM);
#pragma unroll
            for (int tn = 0; tn < 8; tn++) {
                int cb = wn * 64 + tn * 8 + tg * 2;
                float v0 = c[tm][tn][half * 2 + 0] + bias_s[cb];
                float v1 = c[tm][tn][half * 2 + 1] + bias_s[cb + 1];
                if (GELU) {
                    v0 = gelu_exact(v0);
                    v1 = gelu_exact(v1);
                } else {
                    float2 xv = *(const float2*)(xrow + n0 + cb);
                    v0 += xv.x;
                    v1 += xv.y;
                }
                *(float2*)(orow + n0 + cb) = make_float2(v0, v1);
            }
        }
    }
}

// ---------------- finalize: losses + counts ----------------
__global__ void finalize_kernel(float* out, int out_size) {
    if (threadIdx.x == 0) {
        long long base = (long long)T_TOK * H_DIM;
        if ((long long)out_size >= base + 10) {
            double bl = 0.0;
            for (int e = 0; e < E_NUM; e++) {
                double p = g_psum[e] / (double)T_TOK;
                bl += p * p;
            }
            out[base + 0] = (float)((double)E_NUM * bl);
            out[base + 1] = (float)(g_entsum / (double)T_TOK);
            for (int e = 0; e < E_NUM; e++) out[base + 2 + e] = (float)g_cnt[e];
        }
    }
}

// ---------------- launch ----------------
extern "C" void kernel_launch(void* const* d_in, const int* in_sizes, int n_in,
                              void* d_out, int out_size) {
    const float* x  = (const float*)d_in[0];
    const float* Wr = (const float*)d_in[1];
    const float* br = (const float*)d_in[2];
    const float* W1 = (const float*)d_in[3];
    const float* b1 = (const float*)d_in[4];
    const float* W2 = (const float*)d_in[5];
    const float* b2 = (const float*)d_in[6];
    float* out = (float*)d_out;

    const int SMEM_BYTES = 3 * 52224 + 512 + 1024;   // 158,208

    cudaFuncSetAttribute(ffn_gemm<H_DIM, D_DIM, true >,
                         cudaFuncAttributeMaxDynamicSharedMemorySize, SMEM_BYTES);
    cudaFuncSetAttribute(ffn_gemm<D_DIM, H_DIM, false>,
                         cudaFuncAttributeMaxDynamicSharedMemorySize, SMEM_BYTES);

    init_kernel<<<1, 32>>>();
    router_kernel<<<T_TOK / 8, 256>>>(x, Wr, br);
    ffn_gemm<H_DIM, D_DIM, true ><<<dim3(D_DIM / 256, T_TOK / 128, E_NUM), 256, SMEM_BYTES>>>(x, W1, b1, out);
    ffn_gemm<D_DIM, H_DIM, false><<<dim3(H_DIM / 256, T_TOK / 128, E_NUM), 256, SMEM_BYTES>>>(x, W2, b2, out);
    finalize_kernel<<<1, 32>>>(out, out_size);
}